// round 16
// baseline (speedup 1.0000x reference)
#include <cuda_runtime.h>
#include <cuda_bf16.h>
#include <cuda_fp16.h>
#include <math.h>
#include <stdint.h>

#define Bq 4
#define Sq 4096
#define Dq 256
#define Lq 6
#define Vq 32000
#define Hq 1024

// ---------------- scratch (no allocations allowed) ----------------
__device__ __half g_ehalf[(size_t)Bq * Sq * Dq]; // e = ln(wte[tokens]) fp16    8MB
__device__ float g_elast[Bq * Dq];               // e last-token rows fp32
__device__ float g_p0buf[Sq * Dq];               // p_raw = ln(wpe[:S])         4MB
__device__ __nv_bfloat16 g_pA[Sq * Dq];          // bf16(p_raw)                 2MB
__device__ __nv_bfloat16 g_hbf[(size_t)Sq * Hq]; // bf16 FFN hidden             8MB
__device__ __nv_bfloat16 g_w1t[Hq * Dq];         // ff_w1^T  [H][D] bf16
__device__ float g_hlast_part[8 * Hq];
__device__ float g_plast_part[64 * Dq];
__device__ float g_qpart[Lq * 16 * Dq];
__device__ float g_mbuf[Lq * Dq];
__device__ float g_w2m[Lq * Hq];
__device__ float g_abuf[Lq * Sq];
__device__ float g_asum[64 * Lq];
__device__ float g_ctxpart[64 * Lq * Bq * Dq];
__device__ float g_attnout[Lq * Bq * Dq];
__device__ float g_xhat[Bq * Dq];

// ---------------- helpers ----------------
__device__ __forceinline__ uint32_t smem_u32(const void* p) {
    uint32_t a;
    asm("{ .reg .u64 t; cvta.to.shared.u64 t, %1; cvt.u32.u64 %0, t; }" : "=r"(a) : "l"(p));
    return a;
}

__device__ __forceinline__ void ldsm_x4(uint32_t* r, uint32_t addr) {
    asm volatile("ldmatrix.sync.aligned.m8n8.x4.shared.b16 {%0,%1,%2,%3}, [%4];"
                 : "=r"(r[0]), "=r"(r[1]), "=r"(r[2]), "=r"(r[3]) : "r"(addr));
}

__device__ __forceinline__ void mma_bf16(float* c, const uint32_t* a, const uint32_t* b) {
    asm volatile(
        "mma.sync.aligned.m16n8k16.row.col.f32.bf16.bf16.f32 "
        "{%0,%1,%2,%3}, {%4,%5,%6,%7}, {%8,%9}, {%0,%1,%2,%3};"
        : "+f"(c[0]), "+f"(c[1]), "+f"(c[2]), "+f"(c[3])
        : "r"(a[0]), "r"(a[1]), "r"(a[2]), "r"(a[3]), "r"(b[0]), "r"(b[1]));
}

__device__ __forceinline__ void cp_async16(uint32_t saddr, const void* gptr) {
    asm volatile("cp.async.cg.shared.global [%0], [%1], 16;" :: "r"(saddr), "l"(gptr));
}
#define CP_COMMIT() asm volatile("cp.async.commit_group;")
template <int N>
__device__ __forceinline__ void cp_wait() {
    asm volatile("cp.async.wait_group %0;" :: "n"(N));
}

__device__ __forceinline__ float gelu_f(float v) {
    return 0.5f * v * (1.0f + erff(v * 0.70710678118654752f));
}

__device__ __forceinline__ float2 blockReduceSum2_256(float a, float b) {
    __shared__ float sa[8], sb[8];
    int lane = threadIdx.x & 31, w = threadIdx.x >> 5;
#pragma unroll
    for (int o = 16; o; o >>= 1) {
        a += __shfl_xor_sync(0xffffffffu, a, o);
        b += __shfl_xor_sync(0xffffffffu, b, o);
    }
    if (lane == 0) { sa[w] = a; sb[w] = b; }
    __syncthreads();
    if (w == 0) {
        a = (lane < 8) ? sa[lane] : 0.f;
        b = (lane < 8) ? sb[lane] : 0.f;
#pragma unroll
        for (int o = 4; o; o >>= 1) {
            a += __shfl_xor_sync(0xffffffffu, a, o);
            b += __shfl_xor_sync(0xffffffffu, b, o);
        }
        if (lane == 0) { sa[0] = a; sb[0] = b; }
    }
    __syncthreads();
    float ra = sa[0], rb = sb[0];
    __syncthreads();
    return make_float2(ra, rb);
}

// warp-per-row LN core
__device__ __forceinline__ void ln_row(const float* __restrict__ src,
                                       const float* __restrict__ g, int lane,
                                       float4& o0, float4& o1) {
    float4 v0 = *(const float4*)(src + lane * 8);
    float4 v1 = *(const float4*)(src + lane * 8 + 4);
    float s1 = v0.x + v0.y + v0.z + v0.w + v1.x + v1.y + v1.z + v1.w;
    float s2 = v0.x * v0.x + v0.y * v0.y + v0.z * v0.z + v0.w * v0.w +
               v1.x * v1.x + v1.y * v1.y + v1.z * v1.z + v1.w * v1.w;
#pragma unroll
    for (int o = 16; o; o >>= 1) {
        s1 += __shfl_xor_sync(0xffffffffu, s1, o);
        s2 += __shfl_xor_sync(0xffffffffu, s2, o);
    }
    float mean = s1 * (1.0f / Dq);
    float var = s2 * (1.0f / Dq) - mean * mean;
    float rstd = rsqrtf(var + 1e-5f);
    float4 g0 = *(const float4*)(g + lane * 8);
    float4 g1 = *(const float4*)(g + lane * 8 + 4);
    o0.x = (v0.x - mean) * rstd * g0.x;
    o0.y = (v0.y - mean) * rstd * g0.y;
    o0.z = (v0.z - mean) * rstd * g0.z;
    o0.w = (v0.w - mean) * rstd * g0.w;
    o1.x = (v1.x - mean) * rstd * g1.x;
    o1.y = (v1.y - mean) * rstd * g1.y;
    o1.z = (v1.z - mean) * rstd * g1.z;
    o1.w = (v1.w - mean) * rstd * g1.w;
}

__device__ __forceinline__ uint4 pack8h(float4 o0, float4 o1) {
    __half2 h0 = __floats2half2_rn(o0.x, o0.y);
    __half2 h1 = __floats2half2_rn(o0.z, o0.w);
    __half2 h2 = __floats2half2_rn(o1.x, o1.y);
    __half2 h3 = __floats2half2_rn(o1.z, o1.w);
    uint4 u;
    u.x = reinterpret_cast<uint32_t&>(h0);
    u.y = reinterpret_cast<uint32_t&>(h1);
    u.z = reinterpret_cast<uint32_t&>(h2);
    u.w = reinterpret_cast<uint32_t&>(h3);
    return u;
}

// ---------------- K1a (side2): e = ln(wte[tokens]) -> fp16 ---------------
__global__ void __launch_bounds__(256) embed_e_kernel(
    const int* __restrict__ tokens, const float* __restrict__ wte,
    const float* __restrict__ gew) {
    int warp = threadIdx.x >> 5, lane = threadIdx.x & 31;
    int row = blockIdx.x * 8 + warp;
    int tok = __ldg(tokens + row);
    const float* src = wte + (size_t)tok * Dq;
    float4 o0, o1;
    ln_row(src, gew, lane, o0, o1);
    *(uint4*)(g_ehalf + (size_t)row * Dq + lane * 8) = pack8h(o0, o1);
    if ((row & (Sq - 1)) == Sq - 1) {
        int b = row / Sq;
        *(float4*)(g_elast + b * Dq + lane * 8) = o0;
        *(float4*)(g_elast + b * Dq + lane * 8 + 4) = o1;
    }
}

// ---------------- K1b (main): p_raw LN + bf16 + w1 transpose ------------
__global__ void __launch_bounds__(256) embed_p_kernel(
    const float* __restrict__ wpe, const float* __restrict__ gpw,
    const float* __restrict__ w1) {
    int bid = blockIdx.x;
    if (bid >= Sq / 8) {
        int tb = bid - Sq / 8;
        __shared__ float t[32][33];
        int c0 = (tb & 31) * 32, r0 = (tb >> 5) * 32;
        int x = threadIdx.x & 31, y = threadIdx.x >> 5;
#pragma unroll
        for (int i = 0; i < 32; i += 8)
            t[y + i][x] = w1[(size_t)(r0 + y + i) * Hq + c0 + x];
        __syncthreads();
#pragma unroll
        for (int i = 0; i < 32; i += 8)
            g_w1t[(size_t)(c0 + y + i) * Dq + r0 + x] = __float2bfloat16(t[x][y + i]);
        return;
    }
    int warp = threadIdx.x >> 5, lane = threadIdx.x & 31;
    int s = bid * 8 + warp;
    const float* src = wpe + (size_t)s * Dq;
    float* dst = g_p0buf + (size_t)s * Dq;
    __nv_bfloat16* dst16 = g_pA + (size_t)s * Dq;
    float4 o0, o1;
    ln_row(src, gpw, lane, o0, o1);
    *(float4*)(dst + lane * 8) = o0;
    *(float4*)(dst + lane * 8 + 4) = o1;
    __nv_bfloat162 b0 = __floats2bfloat162_rn(o0.x, o0.y);
    __nv_bfloat162 b1 = __floats2bfloat162_rn(o0.z, o0.w);
    __nv_bfloat162 b2 = __floats2bfloat162_rn(o1.x, o1.y);
    __nv_bfloat162 b3 = __floats2bfloat162_rn(o1.z, o1.w);
    uint4 u;
    u.x = reinterpret_cast<uint32_t&>(b0);
    u.y = reinterpret_cast<uint32_t&>(b1);
    u.z = reinterpret_cast<uint32_t&>(b2);
    u.w = reinterpret_cast<uint32_t&>(b3);
    *(uint4*)(dst16 + lane * 8) = u;
}

// ---------------- FFN GEMM1: h = gelu(p_raw @ ff_w1) ----------------------
__global__ void __launch_bounds__(128) ffn_mma_kernel() {
    constexpr int BM = 128, BN = 64, BK = 64, LDS = 72, ST = 3;
    constexpr int Kd = Dq, Nd = Hq, NCH = Kd / BK;
    constexpr int wtM = 64, wtN = 32, MT = 4, NT = 2;

    extern __shared__ __nv_bfloat16 dynsm[];
    __nv_bfloat16* AsBase = dynsm;
    __nv_bfloat16* BsBase = dynsm + ST * BM * LDS;

    int tid = threadIdx.x, wid = tid >> 5, lane = tid & 31;
    int warp_m = wid & 1, warp_n = wid >> 1;
    int m0 = blockIdx.y * BM, n0 = blockIdx.x * BN;

    int a_row = warp_m * wtM + ((lane >> 3) & 1) * 8 + (lane & 7);
    int a_col = (lane >> 4) * 8;
    int b_row = warp_n * wtN + ((lane >> 4) & 1) * 8 + (lane & 7);
    int b_col = ((lane >> 3) & 1) * 8;

    auto load_stage = [&](int st, int k0) {
        __nv_bfloat16* As = AsBase + st * BM * LDS;
        __nv_bfloat16* Bs = BsBase + st * BN * LDS;
#pragma unroll
        for (int i = 0; i < 8; i++) {
            int id = tid + i * 128;
            int r = id >> 3, cc = (id & 7) * 8;
            cp_async16(smem_u32(As + r * LDS + cc), g_pA + (size_t)(m0 + r) * Kd + k0 + cc);
        }
#pragma unroll
        for (int i = 0; i < 4; i++) {
            int id = tid + i * 128;
            int r = id >> 3, cc = (id & 7) * 8;
            cp_async16(smem_u32(Bs + r * LDS + cc), g_w1t + (size_t)(n0 + r) * Kd + k0 + cc);
        }
        CP_COMMIT();
    };

    float c[MT][NT * 2][4] = {};

    load_stage(0, 0);
    load_stage(1, BK);
    for (int ch = 0; ch < NCH; ch++) {
        if (ch == NCH - 1) cp_wait<0>(); else cp_wait<1>();
        __syncthreads();
        if (ch + 2 < NCH) load_stage((ch + 2) % ST, (ch + 2) * BK);
        int st = ch % ST;
        uint32_t As_base = smem_u32(AsBase + st * BM * LDS);
        uint32_t Bs_base = smem_u32(BsBase + st * BN * LDS);
#pragma unroll
        for (int kk = 0; kk < BK / 16; kk++) {
            uint32_t a[MT][4], b[NT][4];
#pragma unroll
            for (int mt = 0; mt < MT; mt++)
                ldsm_x4(a[mt], As_base + ((a_row + mt * 16) * LDS + kk * 16 + a_col) * 2);
#pragma unroll
            for (int nt = 0; nt < NT; nt++)
                ldsm_x4(b[nt], Bs_base + ((b_row + nt * 16) * LDS + kk * 16 + b_col) * 2);
#pragma unroll
            for (int mt = 0; mt < MT; mt++)
#pragma unroll
                for (int nt = 0; nt < NT; nt++) {
                    mma_bf16(c[mt][nt * 2 + 0], a[mt], &b[nt][0]);
                    mma_bf16(c[mt][nt * 2 + 1], a[mt], &b[nt][2]);
                }
        }
    }

    int group = lane >> 2, tg = lane & 3;
#pragma unroll
    for (int mt = 0; mt < MT; mt++) {
#pragma unroll
        for (int nt = 0; nt < NT * 2; nt++) {
#pragma unroll
            for (int half = 0; half < 2; half++) {
                int m = m0 + warp_m * wtM + mt * 16 + group + half * 8;
                int n = n0 + warp_n * wtN + nt * 8 + tg * 2;
                float v0 = gelu_f(c[mt][nt][half * 2 + 0]);
                float v1 = gelu_f(c[mt][nt][half * 2 + 1]);
                __nv_bfloat162 h = __floats2bfloat162_rn(v0, v1);
                *(uint32_t*)&g_hbf[(size_t)m * Nd + n] = reinterpret_cast<uint32_t&>(h);
            }
        }
    }
}

// ---------------- K2a (side, forks at t=0): hlast partials ---------------
// Recomputes p0_last = ln(wpe[S-1])*g_p internally (1KB read, L2-resident).
__global__ void __launch_bounds__(128) hlast_kernel(
    const float* __restrict__ wpe, const float* __restrict__ gpw,
    const float* __restrict__ w1) {
    int hb = blockIdx.x, dc = blockIdx.y;
    int tid = threadIdx.x;
    const float* src = wpe + (size_t)(Sq - 1) * Dq;
    // LN stats over 256 elems with 128 threads (2 each)
    __shared__ float r1[4], r2[4];
    __shared__ float stats[2];
    {
        float x0 = src[tid], x1 = src[tid + 128];
        float s1 = x0 + x1, s2 = x0 * x0 + x1 * x1;
        int lane = tid & 31, w = tid >> 5;
#pragma unroll
        for (int o = 16; o; o >>= 1) {
            s1 += __shfl_xor_sync(0xffffffffu, s1, o);
            s2 += __shfl_xor_sync(0xffffffffu, s2, o);
        }
        if (lane == 0) { r1[w] = s1; r2[w] = s2; }
        __syncthreads();
        if (tid == 0) {
            float a = r1[0] + r1[1] + r1[2] + r1[3];
            float b = r2[0] + r2[1] + r2[2] + r2[3];
            float mean = a * (1.0f / Dq);
            float var = b * (1.0f / Dq) - mean * mean;
            stats[0] = mean;
            stats[1] = rsqrtf(var + 1e-5f);
        }
    }
    __syncthreads();
    __shared__ float p0s[32];
    if (tid < 32) {
        int d = dc * 32 + tid;
        p0s[tid] = (src[d] - stats[0]) * stats[1] * gpw[d];
    }
    __syncthreads();
    int h = hb * 128 + tid;
    const float* w = w1 + (size_t)(dc * 32) * Hq + h;
    float a = 0.f;
#pragma unroll
    for (int i = 0; i < 32; i++) a += p0s[i] * w[(size_t)i * Hq];
    g_hlast_part[dc * Hq + h] = a;
}

// ---------------- K2b (side): plast partials = gelu(hlast) @ W2 ----------
__global__ void plast_kernel(const float* __restrict__ ff_w2) {
    int cc = blockIdx.x;
    int j = threadIdx.x;
    __shared__ float hsm[16];
    if (j < 16) {
        float v = 0.f;
#pragma unroll
        for (int dc = 0; dc < 8; dc++) v += g_hlast_part[dc * Hq + cc * 16 + j];
        hsm[j] = gelu_f(v);
    }
    __syncthreads();
    const float* w = ff_w2 + (size_t)cc * 16 * Dq + j;
    float a = 0.f;
#pragma unroll
    for (int k = 0; k < 16; k++) a += hsm[k] * w[(size_t)k * Dq];
    g_plast_part[cc * Dq + j] = a;
}

// ---------------- K3 (side): partial q = Wq^T p_last (16-way) ------------
// Recomputes p0_last chunk internally (independent of embed_p).
__global__ void __launch_bounds__(256) qk_q_kernel(const float* __restrict__ Wq,
                                                   const float* __restrict__ wpe,
                                                   const float* __restrict__ gpw) {
    int l = blockIdx.x, c = blockIdx.y;
    int tid = threadIdx.x;
    const float* src = wpe + (size_t)(Sq - 1) * Dq;
    float xv = src[tid];
    float2 st = blockReduceSum2_256(xv, xv * xv);
    float mean = st.x * (1.0f / Dq);
    float rstd = rsqrtf(st.y * (1.0f / Dq) - mean * mean + 1e-5f);
    __shared__ float plp[16][17];
    __shared__ float pl[16];
    {
        int i = tid & 15, part = tid >> 4;
        float v = 0.f;
#pragma unroll
        for (int k = 0; k < 4; k++)
            v += g_plast_part[(part * 4 + k) * Dq + c * 16 + i];
        plp[i][part] = v;
    }
    __syncthreads();
    if (tid < 16) {
        int d = c * 16 + tid;
        float v = (src[d] - mean) * rstd * gpw[d];
#pragma unroll
        for (int p = 0; p < 16; p++) v += plp[tid][p];
        pl[tid] = v;
    }
    __syncthreads();
    const float* wq = Wq + (size_t)l * Dq * Dq + (size_t)c * 16 * Dq;
    float acc = 0.f;
#pragma unroll
    for (int i = 0; i < 16; i++) acc += pl[i] * wq[(size_t)i * Dq + tid];
    g_qpart[(l * 16 + c) * Dq + tid] = acc;
}

// ---------------- K4 (side): m_l = Wk_l @ q_l ----------------
__global__ void qk_m_kernel(const float* __restrict__ Wk) {
    int l = blockIdx.x;
    int tid = threadIdx.x;
    int warp = tid >> 5, lane = tid & 31;
    __shared__ float qs[Dq];
    {
        float acc = 0.f;
#pragma unroll
        for (int c = 0; c < 16; c++) acc += g_qpart[(l * 16 + c) * Dq + tid];
        qs[tid] = acc;
    }
    __syncthreads();
    int j = blockIdx.y * 8 + warp;
    const float* wk = Wk + (size_t)l * Dq * Dq + (size_t)j * Dq;
    float m = 0.f;
#pragma unroll
    for (int i = 0; i < 8; i++) {
        int idx = lane + i * 32;
        m += wk[idx] * qs[idx];
    }
#pragma unroll
    for (int o = 16; o; o >>= 1) m += __shfl_xor_sync(0xffffffffu, m, o);
    if (lane == 0) g_mbuf[l * Dq + j] = m;
}

// ---------------- K5 (side): w2m_l = ff_w2 @ m_l -------------------------
__global__ void w2m_kernel(const float* __restrict__ ff_w2) {
    int l = blockIdx.y;
    int tid = threadIdx.x;
    __shared__ float msm[Dq];
    msm[tid] = g_mbuf[l * Dq + tid];
    __syncthreads();
    int warp = tid >> 5, lane = tid & 31;
    int k = blockIdx.x * 8 + warp;
    const float* row = ff_w2 + (size_t)k * Dq;
    float a = 0.f;
#pragma unroll
    for (int i = 0; i < 8; i++) {
        int idx = lane + i * 32;
        a += row[idx] * msm[idx];
    }
#pragma unroll
    for (int o = 16; o; o >>= 1) a += __shfl_xor_sync(0xffffffffu, a, o);
    if (lane == 0) g_w2m[l * Hq + k] = a;
}

// ---------------- K6: scores -> exp (GEMM2 folded in) --------------------
__global__ void __launch_bounds__(256) score_kernel() {
    __shared__ float m_sm[Lq * Dq];
    __shared__ float w_sm[Lq * Hq];
    int tid = threadIdx.x;
    for (int i = tid; i < Lq * Dq; i += 256) m_sm[i] = g_mbuf[i];
    for (int i = tid; i < Lq * Hq; i += 256) w_sm[i] = g_w2m[i];
    __syncthreads();
    int warp = tid >> 5, lane = tid & 31;
    int t = blockIdx.x * 8 + warp;
    const float* p = g_p0buf + (size_t)t * Dq;
    float pv[8];
#pragma unroll
    for (int i = 0; i < 8; i++) pv[i] = p[lane + i * 32];
    const __nv_bfloat162* h2 = (const __nv_bfloat162*)(g_hbf + (size_t)t * Hq);
    float hx[16], hy[16];
#pragma unroll
    for (int i = 0; i < 16; i++) {
        __nv_bfloat162 v = h2[lane + i * 32];
        hx[i] = __bfloat162float(v.x);
        hy[i] = __bfloat162float(v.y);
    }
    float acc[Lq];
#pragma unroll
    for (int l = 0; l < Lq; l++) {
        float a = 0.f;
        const float* mrow = m_sm + l * Dq;
#pragma unroll
        for (int i = 0; i < 8; i++) a += pv[i] * mrow[lane + i * 32];
        const float* wrow = w_sm + l * Hq;
#pragma unroll
        for (int i = 0; i < 16; i++) {
            float2 w2 = *(const float2*)&wrow[2 * (lane + i * 32)];
            a += hx[i] * w2.x + hy[i] * w2.y;
        }
        acc[l] = a;
    }
#pragma unroll
    for (int l = 0; l < Lq; l++) {
#pragma unroll
        for (int o = 16; o; o >>= 1) acc[l] += __shfl_xor_sync(0xffffffffu, acc[l], o);
    }
    if (lane == 0) {
#pragma unroll
        for (int l = 0; l < Lq; l++) g_abuf[l * Sq + t] = expf(acc[l] * 0.0625f);
    }
}

// ---------------- K7: ctx partials (fp16 e) + per-chunk sums -------------
__global__ void ctx_kernel() {
    int chunk = blockIdx.x;
    int b = blockIdx.y;
    int d = threadIdx.x;
    __shared__ float as_[Lq][64];
    for (int i = d; i < Lq * 64; i += 256) {
        int l = i >> 6, t = i & 63;
        as_[l][t] = g_abuf[l * Sq + chunk * 64 + t];
    }
    __syncthreads();
    float acc[Lq] = {};
    const __half* ep = g_ehalf + ((size_t)b * Sq + (size_t)chunk * 64) * Dq + d;
#pragma unroll 4
    for (int t = 0; t < 64; t++) {
        float ev = __half2float(ep[(size_t)t * Dq]);
#pragma unroll
        for (int l = 0; l < Lq; l++) acc[l] += as_[l][t] * ev;
    }
#pragma unroll
    for (int l = 0; l < Lq; l++)
        g_ctxpart[(((size_t)chunk * Lq + l) * Bq + b) * Dq + d] = acc[l];
    if (b == 0 && d < Lq) {
        float s = 0.f;
#pragma unroll 8
        for (int t = 0; t < 64; t++) s += as_[d][t];
        g_asum[chunk * Lq + d] = s;
    }
}

// ---------------- K8: Wv projection (fused reduce + normalize) -----------
__global__ void vproj_kernel(const float* __restrict__ Wv) {
    int l = blockIdx.x, b = blockIdx.y, d = threadIdx.x;
    __shared__ float c[Dq];
    float acc = 0.f;
#pragma unroll
    for (int ch = 0; ch < 64; ch++)
        acc += g_ctxpart[(((size_t)ch * Lq + l) * Bq + b) * Dq + d];
    float ssum = 0.f;
#pragma unroll
    for (int ch = 0; ch < 64; ch++) ssum += g_asum[ch * Lq + l];
    c[d] = acc * (1.0f / ssum);
    __syncthreads();
    const float* wv = Wv + (size_t)l * Dq * Dq;
    float o = 0.f;
#pragma unroll 4
    for (int k = 0; k < Dq; k++) o += c[k] * wv[(size_t)k * Dq + d];
    g_attnout[((size_t)l * Bq + b) * Dq + d] = o;
}

// ---------------- K9: final LN ----------------
__global__ void final_ln_kernel(const float* __restrict__ g_out_w) {
    int b = blockIdx.x, d = threadIdx.x;
    float x = g_elast[b * Dq + d] + g_p0buf[(size_t)(Sq - 1) * Dq + d];
#pragma unroll
    for (int l = 0; l < Lq; l++) x += g_attnout[((size_t)l * Bq + b) * Dq + d];
    float2 r = blockReduceSum2_256(x, x * x);
    float mean = r.x * (1.0f / Dq);
    float var = r.y * (1.0f / Dq) - mean * mean;
    g_xhat[b * Dq + d] = (x - mean) * rsqrtf(var + 1e-5f) * g_out_w[d];
}

// ---------------- K10: logits (fp32 wte, single-pass reductions) ---------
__global__ void logits_kernel(const float* __restrict__ wte,
                              const float* __restrict__ gew,
                              float* __restrict__ out) {
    __shared__ float xs[Bq * Dq];
    __shared__ float gs[Dq];
    int tid = threadIdx.x;
    for (int i = tid; i < Bq * Dq; i += 256) xs[i] = g_xhat[i];
    gs[tid] = gew[tid];
    __syncthreads();
    int warp = tid >> 5, lane = tid & 31;
    int v = blockIdx.x * 8 + warp;
    const float* w = wte + (size_t)v * Dq;
    float s = 0.f, ss = 0.f;
    float A[Bq] = {}, Bv[Bq] = {};
#pragma unroll
    for (int i = 0; i < 8; i++) {
        int idx = lane + i * 32;
        float wv = w[idx];
        float gv = gs[idx];
        s += wv;
        ss += wv * wv;
        float wg = wv * gv;
#pragma unroll
        for (int b = 0; b < Bq; b++) {
            float x = xs[b * Dq + idx];
            A[b] += wg * x;
            Bv[b] += gv * x;
        }
    }
#pragma unroll
    for (int o = 16; o; o >>= 1) {
        s += __shfl_xor_sync(0xffffffffu, s, o);
        ss += __shfl_xor_sync(0xffffffffu, ss, o);
#pragma unroll
        for (int b = 0; b < Bq; b++) {
            A[b] += __shfl_xor_sync(0xffffffffu, A[b], o);
            Bv[b] += __shfl_xor_sync(0xffffffffu, Bv[b], o);
        }
    }
    if (lane == 0) {
        float mean = s * (1.0f / Dq);
        float var = ss * (1.0f / Dq) - mean * mean;
        float rstd = rsqrtf(var + 1e-5f);
#pragma unroll
        for (int b = 0; b < Bq; b++)
            out[(size_t)b * Vq + v] = rstd * (A[b] - mean * Bv[b]);
    }
}

// ---------------- launch: two side streams, chain forks at t=0 -----------
extern "C" void kernel_launch(void* const* d_in, const int* in_sizes, int n_in,
                              void* d_out, int out_size) {
    const int* tokens = (const int*)d_in[0];
    const float* wte = (const float*)d_in[1];
    const float* wpe = (const float*)d_in[2];
    const float* g_e = (const float*)d_in[3];
    const float* g_p = (const float*)d_in[4];
    const float* g_out = (const float*)d_in[5];
    const float* ff_w1 = (const float*)d_in[6];
    const float* ff_w2 = (const float*)d_in[7];
    const float* Wq = (const float*)d_in[8];
    const float* Wk = (const float*)d_in[9];
    const float* Wv = (const float*)d_in[10];
    float* out = (float*)d_out;

    static cudaStream_t s_chain = nullptr, s_e = nullptr;
    static cudaEvent_t ev_start = nullptr, ev_chain = nullptr, ev_e = nullptr;
    if (s_chain == nullptr) {
        cudaStreamCreateWithFlags(&s_chain, cudaStreamNonBlocking);
        cudaStreamCreateWithFlags(&s_e, cudaStreamNonBlocking);
        cudaEventCreateWithFlags(&ev_start, cudaEventDisableTiming);
        cudaEventCreateWithFlags(&ev_chain, cudaEventDisableTiming);
        cudaEventCreateWithFlags(&ev_e, cudaEventDisableTiming);
    }

    constexpr int SM0 = 3 * (128 + 64) * 72 * 2;  // 82944 B
    cudaFuncSetAttribute(ffn_mma_kernel, cudaFuncAttributeMaxDynamicSharedMemorySize, SM0);

    // fork both side streams at entry
    cudaEventRecord(ev_start, 0);
    cudaStreamWaitEvent(s_e, ev_start, 0);
    cudaStreamWaitEvent(s_chain, ev_start, 0);

    // side 2: e-embedding (memory-bound)
    embed_e_kernel<<<Bq * Sq / 8, 256, 0, s_e>>>(tokens, wte, g_e);
    cudaEventRecord(ev_e, s_e);

    // side 1: qk chain (independent of embed_p now)
    hlast_kernel<<<dim3(8, 8), 128, 0, s_chain>>>(wpe, g_p, ff_w1);
    plast_kernel<<<64, 256, 0, s_chain>>>(ff_w2);
    qk_q_kernel<<<dim3(Lq, 16), 256, 0, s_chain>>>(Wq, wpe, g_p);
    qk_m_kernel<<<dim3(Lq, 32), 256, 0, s_chain>>>(Wk);
    w2m_kernel<<<dim3(Hq / 8, Lq), 256, 0, s_chain>>>(ff_w2);
    cudaEventRecord(ev_chain, s_chain);

    // main: p-path LN + w1 transpose, then GEMM1
    embed_p_kernel<<<Sq / 8 + 256, 256>>>(wpe, g_p, ff_w1);
    ffn_mma_kernel<<<dim3(Hq / 64, Sq / 128), 128, SM0>>>();

    // join 1: score needs m, w2m + h
    cudaStreamWaitEvent(0, ev_chain, 0);
    score_kernel<<<Sq / 8, 256>>>();

    // join 2: ctx needs e
    cudaStreamWaitEvent(0, ev_e, 0);
    ctx_kernel<<<dim3(64, Bq), 256>>>();
    vproj_kernel<<<dim3(Lq, Bq), 256>>>(Wv);
    final_ln_kernel<<<Bq, 256>>>(g_out);
    logits_kernel<<<Vq / 8, 256>>>(wte, g_e, out);
}

// round 17
// speedup vs baseline: 1.4736x; 1.4736x over previous
#include <cuda_runtime.h>
#include <cuda_bf16.h>
#include <cuda_fp16.h>
#include <math.h>
#include <stdint.h>

#define Bq 4
#define Sq 4096
#define Dq 256
#define Lq 6
#define Vq 32000
#define Hq 1024

// ---------------- scratch (no allocations allowed) ----------------
__device__ __half g_ehalf[(size_t)Bq * Sq * Dq]; // e = ln(wte[tokens]) fp16    8MB
__device__ float g_elast[Bq * Dq];               // e last-token rows fp32
__device__ float g_p0buf[Sq * Dq];               // p_raw = ln(wpe[:S])         4MB
__device__ __nv_bfloat16 g_pA[Sq * Dq];          // bf16(p_raw)                 2MB
__device__ __nv_bfloat16 g_hbf[(size_t)Sq * Hq]; // bf16 FFN hidden             8MB
__device__ __nv_bfloat16 g_w1t[Hq * Dq];         // ff_w1^T  [H][D] bf16
__device__ float g_hlast_part[8 * Hq];
__device__ float g_plast_part[64 * Dq];
__device__ float g_qpart[Lq * 16 * Dq];
__device__ float g_mbuf[Lq * Dq];
__device__ float g_w2m[Lq * Hq];
__device__ float g_abuf[Lq * Sq];
__device__ float g_asum[64 * Lq];
__device__ float g_ctxpart[64 * Lq * Bq * Dq];
__device__ float g_attnout[Lq * Bq * Dq];
__device__ float g_xhat[Bq * Dq];

// ---------------- helpers ----------------
__device__ __forceinline__ uint32_t smem_u32(const void* p) {
    uint32_t a;
    asm("{ .reg .u64 t; cvta.to.shared.u64 t, %1; cvt.u32.u64 %0, t; }" : "=r"(a) : "l"(p));
    return a;
}

__device__ __forceinline__ void ldsm_x4(uint32_t* r, uint32_t addr) {
    asm volatile("ldmatrix.sync.aligned.m8n8.x4.shared.b16 {%0,%1,%2,%3}, [%4];"
                 : "=r"(r[0]), "=r"(r[1]), "=r"(r[2]), "=r"(r[3]) : "r"(addr));
}

__device__ __forceinline__ void mma_bf16(float* c, const uint32_t* a, const uint32_t* b) {
    asm volatile(
        "mma.sync.aligned.m16n8k16.row.col.f32.bf16.bf16.f32 "
        "{%0,%1,%2,%3}, {%4,%5,%6,%7}, {%8,%9}, {%0,%1,%2,%3};"
        : "+f"(c[0]), "+f"(c[1]), "+f"(c[2]), "+f"(c[3])
        : "r"(a[0]), "r"(a[1]), "r"(a[2]), "r"(a[3]), "r"(b[0]), "r"(b[1]));
}

__device__ __forceinline__ void cp_async16(uint32_t saddr, const void* gptr) {
    asm volatile("cp.async.cg.shared.global [%0], [%1], 16;" :: "r"(saddr), "l"(gptr));
}
#define CP_COMMIT() asm volatile("cp.async.commit_group;")
template <int N>
__device__ __forceinline__ void cp_wait() {
    asm volatile("cp.async.wait_group %0;" :: "n"(N));
}

__device__ __forceinline__ float gelu_f(float v) {
    return 0.5f * v * (1.0f + erff(v * 0.70710678118654752f));
}

__device__ __forceinline__ float2 blockReduceSum2_256(float a, float b) {
    __shared__ float sa[8], sb[8];
    int lane = threadIdx.x & 31, w = threadIdx.x >> 5;
#pragma unroll
    for (int o = 16; o; o >>= 1) {
        a += __shfl_xor_sync(0xffffffffu, a, o);
        b += __shfl_xor_sync(0xffffffffu, b, o);
    }
    if (lane == 0) { sa[w] = a; sb[w] = b; }
    __syncthreads();
    if (w == 0) {
        a = (lane < 8) ? sa[lane] : 0.f;
        b = (lane < 8) ? sb[lane] : 0.f;
#pragma unroll
        for (int o = 4; o; o >>= 1) {
            a += __shfl_xor_sync(0xffffffffu, a, o);
            b += __shfl_xor_sync(0xffffffffu, b, o);
        }
        if (lane == 0) { sa[0] = a; sb[0] = b; }
    }
    __syncthreads();
    float ra = sa[0], rb = sb[0];
    __syncthreads();
    return make_float2(ra, rb);
}

// warp-per-row LN core
__device__ __forceinline__ void ln_row(const float* __restrict__ src,
                                       const float* __restrict__ g, int lane,
                                       float4& o0, float4& o1) {
    float4 v0 = *(const float4*)(src + lane * 8);
    float4 v1 = *(const float4*)(src + lane * 8 + 4);
    float s1 = v0.x + v0.y + v0.z + v0.w + v1.x + v1.y + v1.z + v1.w;
    float s2 = v0.x * v0.x + v0.y * v0.y + v0.z * v0.z + v0.w * v0.w +
               v1.x * v1.x + v1.y * v1.y + v1.z * v1.z + v1.w * v1.w;
#pragma unroll
    for (int o = 16; o; o >>= 1) {
        s1 += __shfl_xor_sync(0xffffffffu, s1, o);
        s2 += __shfl_xor_sync(0xffffffffu, s2, o);
    }
    float mean = s1 * (1.0f / Dq);
    float var = s2 * (1.0f / Dq) - mean * mean;
    float rstd = rsqrtf(var + 1e-5f);
    float4 g0 = *(const float4*)(g + lane * 8);
    float4 g1 = *(const float4*)(g + lane * 8 + 4);
    o0.x = (v0.x - mean) * rstd * g0.x;
    o0.y = (v0.y - mean) * rstd * g0.y;
    o0.z = (v0.z - mean) * rstd * g0.z;
    o0.w = (v0.w - mean) * rstd * g0.w;
    o1.x = (v1.x - mean) * rstd * g1.x;
    o1.y = (v1.y - mean) * rstd * g1.y;
    o1.z = (v1.z - mean) * rstd * g1.z;
    o1.w = (v1.w - mean) * rstd * g1.w;
}

__device__ __forceinline__ uint4 pack8h(float4 o0, float4 o1) {
    __half2 h0 = __floats2half2_rn(o0.x, o0.y);
    __half2 h1 = __floats2half2_rn(o0.z, o0.w);
    __half2 h2 = __floats2half2_rn(o1.x, o1.y);
    __half2 h3 = __floats2half2_rn(o1.z, o1.w);
    uint4 u;
    u.x = reinterpret_cast<uint32_t&>(h0);
    u.y = reinterpret_cast<uint32_t&>(h1);
    u.z = reinterpret_cast<uint32_t&>(h2);
    u.w = reinterpret_cast<uint32_t&>(h3);
    return u;
}

// ---------------- K1a (side2): e = ln(wte[tokens]) -> fp16 ---------------
__global__ void __launch_bounds__(256) embed_e_kernel(
    const int* __restrict__ tokens, const float* __restrict__ wte,
    const float* __restrict__ gew) {
    int warp = threadIdx.x >> 5, lane = threadIdx.x & 31;
    int row = blockIdx.x * 8 + warp;
    int tok = __ldg(tokens + row);
    const float* src = wte + (size_t)tok * Dq;
    float4 o0, o1;
    ln_row(src, gew, lane, o0, o1);
    *(uint4*)(g_ehalf + (size_t)row * Dq + lane * 8) = pack8h(o0, o1);
    if ((row & (Sq - 1)) == Sq - 1) {
        int b = row / Sq;
        *(float4*)(g_elast + b * Dq + lane * 8) = o0;
        *(float4*)(g_elast + b * Dq + lane * 8 + 4) = o1;
    }
}

// ---------------- K1b (main): p_raw LN + bf16 + w1 transpose ------------
__global__ void __launch_bounds__(256) embed_p_kernel(
    const float* __restrict__ wpe, const float* __restrict__ gpw,
    const float* __restrict__ w1) {
    int bid = blockIdx.x;
    if (bid >= Sq / 8) {
        int tb = bid - Sq / 8;
        __shared__ float t[32][33];
        int c0 = (tb & 31) * 32, r0 = (tb >> 5) * 32;
        int x = threadIdx.x & 31, y = threadIdx.x >> 5;
#pragma unroll
        for (int i = 0; i < 32; i += 8)
            t[y + i][x] = w1[(size_t)(r0 + y + i) * Hq + c0 + x];
        __syncthreads();
#pragma unroll
        for (int i = 0; i < 32; i += 8)
            g_w1t[(size_t)(c0 + y + i) * Dq + r0 + x] = __float2bfloat16(t[x][y + i]);
        return;
    }
    int warp = threadIdx.x >> 5, lane = threadIdx.x & 31;
    int s = bid * 8 + warp;
    const float* src = wpe + (size_t)s * Dq;
    float* dst = g_p0buf + (size_t)s * Dq;
    __nv_bfloat16* dst16 = g_pA + (size_t)s * Dq;
    float4 o0, o1;
    ln_row(src, gpw, lane, o0, o1);
    *(float4*)(dst + lane * 8) = o0;
    *(float4*)(dst + lane * 8 + 4) = o1;
    __nv_bfloat162 b0 = __floats2bfloat162_rn(o0.x, o0.y);
    __nv_bfloat162 b1 = __floats2bfloat162_rn(o0.z, o0.w);
    __nv_bfloat162 b2 = __floats2bfloat162_rn(o1.x, o1.y);
    __nv_bfloat162 b3 = __floats2bfloat162_rn(o1.z, o1.w);
    uint4 u;
    u.x = reinterpret_cast<uint32_t&>(b0);
    u.y = reinterpret_cast<uint32_t&>(b1);
    u.z = reinterpret_cast<uint32_t&>(b2);
    u.w = reinterpret_cast<uint32_t&>(b3);
    *(uint4*)(dst16 + lane * 8) = u;
}

// ---------------- FFN GEMM1: h = gelu(p_raw @ ff_w1) ----------------------
__global__ void __launch_bounds__(128) ffn_mma_kernel() {
    constexpr int BM = 128, BN = 64, BK = 64, LDS = 72, ST = 3;
    constexpr int Kd = Dq, Nd = Hq, NCH = Kd / BK;
    constexpr int wtM = 64, wtN = 32, MT = 4, NT = 2;

    extern __shared__ __nv_bfloat16 dynsm[];
    __nv_bfloat16* AsBase = dynsm;
    __nv_bfloat16* BsBase = dynsm + ST * BM * LDS;

    int tid = threadIdx.x, wid = tid >> 5, lane = tid & 31;
    int warp_m = wid & 1, warp_n = wid >> 1;
    int m0 = blockIdx.y * BM, n0 = blockIdx.x * BN;

    int a_row = warp_m * wtM + ((lane >> 3) & 1) * 8 + (lane & 7);
    int a_col = (lane >> 4) * 8;
    int b_row = warp_n * wtN + ((lane >> 4) & 1) * 8 + (lane & 7);
    int b_col = ((lane >> 3) & 1) * 8;

    auto load_stage = [&](int st, int k0) {
        __nv_bfloat16* As = AsBase + st * BM * LDS;
        __nv_bfloat16* Bs = BsBase + st * BN * LDS;
#pragma unroll
        for (int i = 0; i < 8; i++) {
            int id = tid + i * 128;
            int r = id >> 3, cc = (id & 7) * 8;
            cp_async16(smem_u32(As + r * LDS + cc), g_pA + (size_t)(m0 + r) * Kd + k0 + cc);
        }
#pragma unroll
        for (int i = 0; i < 4; i++) {
            int id = tid + i * 128;
            int r = id >> 3, cc = (id & 7) * 8;
            cp_async16(smem_u32(Bs + r * LDS + cc), g_w1t + (size_t)(n0 + r) * Kd + k0 + cc);
        }
        CP_COMMIT();
    };

    float c[MT][NT * 2][4] = {};

    load_stage(0, 0);
    load_stage(1, BK);
    for (int ch = 0; ch < NCH; ch++) {
        if (ch == NCH - 1) cp_wait<0>(); else cp_wait<1>();
        __syncthreads();
        if (ch + 2 < NCH) load_stage((ch + 2) % ST, (ch + 2) * BK);
        int st = ch % ST;
        uint32_t As_base = smem_u32(AsBase + st * BM * LDS);
        uint32_t Bs_base = smem_u32(BsBase + st * BN * LDS);
#pragma unroll
        for (int kk = 0; kk < BK / 16; kk++) {
            uint32_t a[MT][4], b[NT][4];
#pragma unroll
            for (int mt = 0; mt < MT; mt++)
                ldsm_x4(a[mt], As_base + ((a_row + mt * 16) * LDS + kk * 16 + a_col) * 2);
#pragma unroll
            for (int nt = 0; nt < NT; nt++)
                ldsm_x4(b[nt], Bs_base + ((b_row + nt * 16) * LDS + kk * 16 + b_col) * 2);
#pragma unroll
            for (int mt = 0; mt < MT; mt++)
#pragma unroll
                for (int nt = 0; nt < NT; nt++) {
                    mma_bf16(c[mt][nt * 2 + 0], a[mt], &b[nt][0]);
                    mma_bf16(c[mt][nt * 2 + 1], a[mt], &b[nt][2]);
                }
        }
    }

    int group = lane >> 2, tg = lane & 3;
#pragma unroll
    for (int mt = 0; mt < MT; mt++) {
#pragma unroll
        for (int nt = 0; nt < NT * 2; nt++) {
#pragma unroll
            for (int half = 0; half < 2; half++) {
                int m = m0 + warp_m * wtM + mt * 16 + group + half * 8;
                int n = n0 + warp_n * wtN + nt * 8 + tg * 2;
                float v0 = gelu_f(c[mt][nt][half * 2 + 0]);
                float v1 = gelu_f(c[mt][nt][half * 2 + 1]);
                __nv_bfloat162 h = __floats2bfloat162_rn(v0, v1);
                *(uint32_t*)&g_hbf[(size_t)m * Nd + n] = reinterpret_cast<uint32_t&>(h);
            }
        }
    }
}

// ---------------- K2a (side): hlast partials = p0[S-1] @ W1 --------------
__global__ void hlast_kernel(const float* __restrict__ w1) {
    int hb = blockIdx.x, dc = blockIdx.y;
    int tid = threadIdx.x;
    __shared__ float p0s[32];
    if (tid < 32) p0s[tid] = g_p0buf[(size_t)(Sq - 1) * Dq + dc * 32 + tid];
    __syncthreads();
    int h = hb * 128 + tid;
    const float* w = w1 + (size_t)(dc * 32) * Hq + h;
    float a = 0.f;
#pragma unroll
    for (int i = 0; i < 32; i++) a += p0s[i] * w[(size_t)i * Hq];
    g_hlast_part[dc * Hq + h] = a;
}

// ---------------- K2b (side): plast partials = gelu(hlast) @ W2 ----------
__global__ void plast_kernel(const float* __restrict__ ff_w2) {
    int cc = blockIdx.x;
    int j = threadIdx.x;
    __shared__ float hsm[16];
    if (j < 16) {
        float v = 0.f;
#pragma unroll
        for (int dc = 0; dc < 8; dc++) v += g_hlast_part[dc * Hq + cc * 16 + j];
        hsm[j] = gelu_f(v);
    }
    __syncthreads();
    const float* w = ff_w2 + (size_t)cc * 16 * Dq + j;
    float a = 0.f;
#pragma unroll
    for (int k = 0; k < 16; k++) a += hsm[k] * w[(size_t)k * Dq];
    g_plast_part[cc * Dq + j] = a;
}

// ---------------- K3 (side): partial q = Wq^T p_last (16-way) ------------
__global__ void __launch_bounds__(256) qk_q_kernel(const float* __restrict__ Wq) {
    int l = blockIdx.x, c = blockIdx.y;
    int tid = threadIdx.x;
    __shared__ float plp[16][17];
    __shared__ float pl[16];
    {
        int i = tid & 15, part = tid >> 4;
        float v = 0.f;
#pragma unroll
        for (int k = 0; k < 4; k++)
            v += g_plast_part[(part * 4 + k) * Dq + c * 16 + i];
        plp[i][part] = v;
    }
    __syncthreads();
    if (tid < 16) {
        float v = g_p0buf[(size_t)(Sq - 1) * Dq + c * 16 + tid];
#pragma unroll
        for (int p = 0; p < 16; p++) v += plp[tid][p];
        pl[tid] = v;
    }
    __syncthreads();
    const float* wq = Wq + (size_t)l * Dq * Dq + (size_t)c * 16 * Dq;
    float acc = 0.f;
#pragma unroll
    for (int i = 0; i < 16; i++) acc += pl[i] * wq[(size_t)i * Dq + tid];
    g_qpart[(l * 16 + c) * Dq + tid] = acc;
}

// ---------------- K4 (side): m_l = Wk_l @ q_l ----------------
__global__ void qk_m_kernel(const float* __restrict__ Wk) {
    int l = blockIdx.x;
    int tid = threadIdx.x;
    int warp = tid >> 5, lane = tid & 31;
    __shared__ float qs[Dq];
    {
        float acc = 0.f;
#pragma unroll
        for (int c = 0; c < 16; c++) acc += g_qpart[(l * 16 + c) * Dq + tid];
        qs[tid] = acc;
    }
    __syncthreads();
    int j = blockIdx.y * 8 + warp;
    const float* wk = Wk + (size_t)l * Dq * Dq + (size_t)j * Dq;
    float m = 0.f;
#pragma unroll
    for (int i = 0; i < 8; i++) {
        int idx = lane + i * 32;
        m += wk[idx] * qs[idx];
    }
#pragma unroll
    for (int o = 16; o; o >>= 1) m += __shfl_xor_sync(0xffffffffu, m, o);
    if (lane == 0) g_mbuf[l * Dq + j] = m;
}

// ---------------- K5 (side): w2m_l = ff_w2 @ m_l -------------------------
__global__ void w2m_kernel(const float* __restrict__ ff_w2) {
    int l = blockIdx.y;
    int tid = threadIdx.x;
    __shared__ float msm[Dq];
    msm[tid] = g_mbuf[l * Dq + tid];
    __syncthreads();
    int warp = tid >> 5, lane = tid & 31;
    int k = blockIdx.x * 8 + warp;
    const float* row = ff_w2 + (size_t)k * Dq;
    float a = 0.f;
#pragma unroll
    for (int i = 0; i < 8; i++) {
        int idx = lane + i * 32;
        a += row[idx] * msm[idx];
    }
#pragma unroll
    for (int o = 16; o; o >>= 1) a += __shfl_xor_sync(0xffffffffu, a, o);
    if (lane == 0) g_w2m[l * Hq + k] = a;
}

// ---------------- K6: scores -> exp (bf16 p + h, GEMM2 folded in) --------
__global__ void __launch_bounds__(256) score_kernel() {
    __shared__ float m_sm[Lq * Dq];
    __shared__ float w_sm[Lq * Hq];
    int tid = threadIdx.x;
    for (int i = tid; i < Lq * Dq; i += 256) m_sm[i] = g_mbuf[i];
    for (int i = tid; i < Lq * Hq; i += 256) w_sm[i] = g_w2m[i];
    __syncthreads();
    int warp = tid >> 5, lane = tid & 31;
    int t = blockIdx.x * 8 + warp;
    const __nv_bfloat162* p2 = (const __nv_bfloat162*)(g_pA + (size_t)t * Dq);
    float px[4], py[4];
#pragma unroll
    for (int i = 0; i < 4; i++) {
        __nv_bfloat162 v = p2[lane + i * 32];
        px[i] = __bfloat162float(v.x);
        py[i] = __bfloat162float(v.y);
    }
    const __nv_bfloat162* h2 = (const __nv_bfloat162*)(g_hbf + (size_t)t * Hq);
    float hx[16], hy[16];
#pragma unroll
    for (int i = 0; i < 16; i++) {
        __nv_bfloat162 v = h2[lane + i * 32];
        hx[i] = __bfloat162float(v.x);
        hy[i] = __bfloat162float(v.y);
    }
    float acc[Lq];
#pragma unroll
    for (int l = 0; l < Lq; l++) {
        float a = 0.f;
        const float* mrow = m_sm + l * Dq;
#pragma unroll
        for (int i = 0; i < 4; i++) {
            float2 m2 = *(const float2*)&mrow[2 * (lane + i * 32)];
            a += px[i] * m2.x + py[i] * m2.y;
        }
        const float* wrow = w_sm + l * Hq;
#pragma unroll
        for (int i = 0; i < 16; i++) {
            float2 w2 = *(const float2*)&wrow[2 * (lane + i * 32)];
            a += hx[i] * w2.x + hy[i] * w2.y;
        }
        acc[l] = a;
    }
#pragma unroll
    for (int l = 0; l < Lq; l++) {
#pragma unroll
        for (int o = 16; o; o >>= 1) acc[l] += __shfl_xor_sync(0xffffffffu, acc[l], o);
    }
    if (lane == 0) {
#pragma unroll
        for (int l = 0; l < Lq; l++) g_abuf[l * Sq + t] = expf(acc[l] * 0.0625f);
    }
}

// ---------------- K7: ctx partials (fp16 e) + per-chunk sums -------------
__global__ void ctx_kernel() {
    int chunk = blockIdx.x;
    int b = blockIdx.y;
    int d = threadIdx.x;
    __shared__ float as_[Lq][64];
    for (int i = d; i < Lq * 64; i += 256) {
        int l = i >> 6, t = i & 63;
        as_[l][t] = g_abuf[l * Sq + chunk * 64 + t];
    }
    __syncthreads();
    float acc[Lq] = {};
    const __half* ep = g_ehalf + ((size_t)b * Sq + (size_t)chunk * 64) * Dq + d;
#pragma unroll 4
    for (int t = 0; t < 64; t++) {
        float ev = __half2float(ep[(size_t)t * Dq]);
#pragma unroll
        for (int l = 0; l < Lq; l++) acc[l] += as_[l][t] * ev;
    }
#pragma unroll
    for (int l = 0; l < Lq; l++)
        g_ctxpart[(((size_t)chunk * Lq + l) * Bq + b) * Dq + d] = acc[l];
    if (b == 0 && d < Lq) {
        float s = 0.f;
#pragma unroll 8
        for (int t = 0; t < 64; t++) s += as_[d][t];
        g_asum[chunk * Lq + d] = s;
    }
}

// ---------------- K8: Wv projection (fused reduce + normalize) -----------
__global__ void vproj_kernel(const float* __restrict__ Wv) {
    int l = blockIdx.x, b = blockIdx.y, d = threadIdx.x;
    __shared__ float c[Dq];
    float acc = 0.f;
#pragma unroll
    for (int ch = 0; ch < 64; ch++)
        acc += g_ctxpart[(((size_t)ch * Lq + l) * Bq + b) * Dq + d];
    float ssum = 0.f;
#pragma unroll
    for (int ch = 0; ch < 64; ch++) ssum += g_asum[ch * Lq + l];
    c[d] = acc * (1.0f / ssum);
    __syncthreads();
    const float* wv = Wv + (size_t)l * Dq * Dq;
    float o = 0.f;
#pragma unroll 4
    for (int k = 0; k < Dq; k++) o += c[k] * wv[(size_t)k * Dq + d];
    g_attnout[((size_t)l * Bq + b) * Dq + d] = o;
}

// ---------------- K9: final LN ----------------
__global__ void final_ln_kernel(const float* __restrict__ g_out_w) {
    int b = blockIdx.x, d = threadIdx.x;
    float x = g_elast[b * Dq + d] + g_p0buf[(size_t)(Sq - 1) * Dq + d];
#pragma unroll
    for (int l = 0; l < Lq; l++) x += g_attnout[((size_t)l * Bq + b) * Dq + d];
    float2 r = blockReduceSum2_256(x, x * x);
    float mean = r.x * (1.0f / Dq);
    float var = r.y * (1.0f / Dq) - mean * mean;
    g_xhat[b * Dq + d] = (x - mean) * rsqrtf(var + 1e-5f) * g_out_w[d];
}

// ---------------- K10: logits (fp32 wte, single-pass reductions) ---------
__global__ void logits_kernel(const float* __restrict__ wte,
                              const float* __restrict__ gew,
                              float* __restrict__ out) {
    __shared__ float xs[Bq * Dq];
    __shared__ float gs[Dq];
    int tid = threadIdx.x;
    for (int i = tid; i < Bq * Dq; i += 256) xs[i] = g_xhat[i];
    gs[tid] = gew[tid];
    __syncthreads();
    int warp = tid >> 5, lane = tid & 31;
    int v = blockIdx.x * 8 + warp;
    const float* w = wte + (size_t)v * Dq;
    float s = 0.f, ss = 0.f;
    float A[Bq] = {}, Bv[Bq] = {};
#pragma unroll
    for (int i = 0; i < 8; i++) {
        int idx = lane + i * 32;
        float wv = w[idx];
        float gv = gs[idx];
        s += wv;
        ss += wv * wv;
        float wg = wv * gv;
#pragma unroll
        for (int b = 0; b < Bq; b++) {
            float x = xs[b * Dq + idx];
            A[b] += wg * x;
            Bv[b] += gv * x;
        }
    }
#pragma unroll
    for (int o = 16; o; o >>= 1) {
        s += __shfl_xor_sync(0xffffffffu, s, o);
        ss += __shfl_xor_sync(0xffffffffu, ss, o);
#pragma unroll
        for (int b = 0; b < Bq; b++) {
            A[b] += __shfl_xor_sync(0xffffffffu, A[b], o);
            Bv[b] += __shfl_xor_sync(0xffffffffu, Bv[b], o);
        }
    }
    if (lane == 0) {
        float mean = s * (1.0f / Dq);
        float var = ss * (1.0f / Dq) - mean * mean;
        float rstd = rsqrtf(var + 1e-5f);
#pragma unroll
        for (int b = 0; b < Bq; b++)
            out[(size_t)b * Vq + v] = rstd * (A[b] - mean * Bv[b]);
    }
}

// ---------------- launch: R15 topology (chain forks after embed_p) -------
extern "C" void kernel_launch(void* const* d_in, const int* in_sizes, int n_in,
                              void* d_out, int out_size) {
    const int* tokens = (const int*)d_in[0];
    const float* wte = (const float*)d_in[1];
    const float* wpe = (const float*)d_in[2];
    const float* g_e = (const float*)d_in[3];
    const float* g_p = (const float*)d_in[4];
    const float* g_out = (const float*)d_in[5];
    const float* ff_w1 = (const float*)d_in[6];
    const float* ff_w2 = (const float*)d_in[7];
    const float* Wq = (const float*)d_in[8];
    const float* Wk = (const float*)d_in[9];
    const float* Wv = (const float*)d_in[10];
    float* out = (float*)d_out;

    static cudaStream_t s_chain = nullptr, s_e = nullptr;
    static cudaEvent_t ev_start = nullptr, ev_p = nullptr, ev_chain = nullptr, ev_e = nullptr;
    if (s_chain == nullptr) {
        cudaStreamCreateWithFlags(&s_chain, cudaStreamNonBlocking);
        cudaStreamCreateWithFlags(&s_e, cudaStreamNonBlocking);
        cudaEventCreateWithFlags(&ev_start, cudaEventDisableTiming);
        cudaEventCreateWithFlags(&ev_p, cudaEventDisableTiming);
        cudaEventCreateWithFlags(&ev_chain, cudaEventDisableTiming);
        cudaEventCreateWithFlags(&ev_e, cudaEventDisableTiming);
    }

    constexpr int SM0 = 3 * (128 + 64) * 72 * 2;  // 82944 B
    cudaFuncSetAttribute(ffn_mma_kernel, cudaFuncAttributeMaxDynamicSharedMemorySize, SM0);

    // fork e-stream at entry (independent of p path)
    cudaEventRecord(ev_start, 0);
    cudaStreamWaitEvent(s_e, ev_start, 0);
    embed_e_kernel<<<Bq * Sq / 8, 256, 0, s_e>>>(tokens, wte, g_e);
    cudaEventRecord(ev_e, s_e);

    // main: p-path LN + w1 transpose
    embed_p_kernel<<<Sq / 8 + 256, 256>>>(wpe, g_p, ff_w1);

    // fork chain stream after embed_p
    cudaEventRecord(ev_p, 0);
    cudaStreamWaitEvent(s_chain, ev_p, 0);
    hlast_kernel<<<dim3(8, 8), 128, 0, s_chain>>>(ff_w1);
    plast_kernel<<<64, 256, 0, s_chain>>>(ff_w2);
    qk_q_kernel<<<dim3(Lq, 16), 256, 0, s_chain>>>(Wq);
    qk_m_kernel<<<dim3(Lq, 32), 256, 0, s_chain>>>(Wk);
    w2m_kernel<<<dim3(Hq / 8, Lq), 256, 0, s_chain>>>(ff_w2);
    cudaEventRecord(ev_chain, s_chain);

    // main: GEMM1 concurrently
    ffn_mma_kernel<<<dim3(Hq / 64, Sq / 128), 128, SM0>>>();

    // join 1: score needs m, w2m + h
    cudaStreamWaitEvent(0, ev_chain, 0);
    score_kernel<<<Sq / 8, 256>>>();

    // join 2: ctx needs e
    cudaStreamWaitEvent(0, ev_e, 0);
    ctx_kernel<<<dim3(64, Bq), 256>>>();
    vproj_kernel<<<dim3(Lq, Bq), 256>>>(Wv);
    final_ln_kernel<<<Bq, 256>>>(g_out);
    logits_kernel<<<Vq / 8, 256>>>(wte, g_e, out);
}